// round 8
// baseline (speedup 1.0000x reference)
#include <cuda_runtime.h>
#include <cstdint>

#define NB 16      // batch
#define NS 512     // seq
#define NH 384     // hidden
#define NL 2000    // max_mel_len
#define NBINS 256
#define H4 (NH/4)  // 96 float4 per row

#define TR 16                       // tile rows per CTA (125 tiles per batch row)
#define TILE_BYTES (TR * NH * 4)    // 24576
#define NT 384                      // threads per CTA

// Single fused kernel. grid (125, 16), block (96, 4).
// Each CTA redundantly recomputes the per-batch-row prep (duration scan,
// pitch/energy means) in smem, derives seg indices for its 16 rows by
// binary search over the cumsum, builds the tile, TMA-bulk-stores it.
__global__ void __launch_bounds__(NT) fused_kernel(
    const float4* __restrict__ enc,
    const float*  __restrict__ ldur,
    const float*  __restrict__ pitch,
    const float*  __restrict__ energy,
    const float4* __restrict__ pemb,
    const float4* __restrict__ eemb,
    float4* __restrict__ out,
    float* __restrict__ out_tail, int write_tail)
{
    __shared__ __align__(128) float4 tile[TR * H4];   // 24 KB
    __shared__ int   sc[NS];                          // cumsum (2 KB)
    __shared__ float wred[2][12];
    __shared__ int   s_idx[2];                        // pidx, eidx
    __shared__ int   sseg[TR];

    const int q   = threadIdx.x;                // 0..95
    const int yy  = threadIdx.y;                // 0..3
    const int tid = yy * 96 + q;                // 0..383
    const int b   = blockIdx.y;                 // 0..15
    const int l0  = blockIdx.x * TR;            // tile base row
    const int r0  = yy * 4;                     // my 4 consecutive rows
    const int lane = tid & 31;
    const int warp = tid >> 5;                  // 0..11

    // ---- durations into smem + pitch/energy partial sums ----
    float ps = 0.f, es = 0.f;
    #pragma unroll
    for (int i = tid; i < NS; i += NT) {
        const float ld = ldur[b * NS + i];
        sc[i] = (int)fmaxf(rintf(expf(ld) - 1.0f), 0.0f);
        ps += pitch[b * NS + i];
        es += energy[b * NS + i];
    }
    // warp-reduce the partial sums
    #pragma unroll
    for (int off = 16; off > 0; off >>= 1) {
        ps += __shfl_xor_sync(0xffffffffu, ps, off);
        es += __shfl_xor_sync(0xffffffffu, es, off);
    }
    if (lane == 0) { wred[0][warp] = ps; wred[1][warp] = es; }
    __syncthreads();

    // ---- Kogge-Stone inclusive scan over 512 (384 threads, 2 elems) ----
    #pragma unroll
    for (int off = 1; off < NS; off <<= 1) {
        const int i1 = tid + NT;                       // only tid<128 valid
        int v0 = (tid >= off) ? sc[tid - off] : 0;
        int v1 = 0;
        if (i1 < NS) v1 = (i1 >= off) ? sc[i1 - off] : 0;
        __syncthreads();
        sc[tid] += v0;
        if (i1 < NS) sc[i1] += v1;
        __syncthreads();
    }
    const int total = sc[NS - 1];
    const int ml    = min(total, NL);

    // ---- finalize means -> bin indices ----
    if (tid < 2) {
        float s = 0.f;
        #pragma unroll
        for (int i = 0; i < 12; i++) s += wred[tid][i];
        s_idx[tid] = min(max((int)(s * (1.0f / NS)), 0), NBINS - 1);
    }
    if (write_tail && blockIdx.x == 0 && tid == 2)
        out_tail[b] = (float)ml;

    // ---- seg for my tile rows: lower_bound(cum, l) (first cum[s] > l) ----
    if (tid < TR) {
        const int l = l0 + tid;
        int s = 0;
        #pragma unroll
        for (int step = 256; step > 0; step >>= 1)
            if (sc[s + step - 1] <= l) s += step;
        sseg[tid] = min(s, NS - 1);
    }
    __syncthreads();

    // ---- combined embedding value for my column ----
    const int pidx = s_idx[0];
    const int eidx = s_idx[1];
    const float4 pv = __ldg(&pemb[pidx * H4 + q]);
    const float4 evv = __ldg(&eemb[eidx * H4 + q]);
    float4 c;
    c.x = pv.x + evv.x; c.y = pv.y + evv.y;
    c.z = pv.z + evv.z; c.w = pv.w + evv.w;

    // ---- gather + mask + STS (front-batched loads) ----
    const float4* __restrict__ encb = enc + b * (NS * H4);
    int sv[4];
    #pragma unroll
    for (int i = 0; i < 4; i++) sv[i] = sseg[r0 + i];

    float4 ev[4];
    #pragma unroll
    for (int i = 0; i < 4; i++)
        ev[i] = __ldg(&encb[sv[i] * H4 + q]);

    #pragma unroll
    for (int i = 0; i < 4; i++) {
        const float m = (l0 + r0 + i < ml) ? 1.0f : 0.0f;
        float4 v;
        v.x = fmaf(m, ev[i].x, c.x);
        v.y = fmaf(m, ev[i].y, c.y);
        v.z = fmaf(m, ev[i].z, c.z);
        v.w = fmaf(m, ev[i].w, c.w);
        tile[(r0 + i) * H4 + q] = v;
    }
    __syncthreads();

    // ---- single 24KB TMA bulk store ----
    if (tid == 0) {
        uint32_t saddr;
        asm("{ .reg .u64 t; cvta.to.shared.u64 t, %1; cvt.u32.u64 %0, t; }"
            : "=r"(saddr) : "l"((const void*)tile));
        const float4* gdst = out + (size_t)(b * NL + l0) * H4;
        asm volatile("fence.proxy.async.shared::cta;" ::: "memory");
        asm volatile(
            "cp.async.bulk.global.shared::cta.bulk_group [%0], [%1], %2;"
            :: "l"(gdst), "r"(saddr), "n"(TILE_BYTES) : "memory");
        asm volatile("cp.async.bulk.commit_group;" ::: "memory");
        asm volatile("cp.async.bulk.wait_group 0;" ::: "memory");
    }
}

extern "C" void kernel_launch(void* const* d_in, const int* in_sizes, int n_in,
                              void* d_out, int out_size)
{
    const float* enc   = (const float*)d_in[0];  // (B,S,H)
    const float* ldur  = (const float*)d_in[1];  // (B,S)
    const float* pitch = (const float*)d_in[2];  // (B,S)
    const float* energ = (const float*)d_in[3];  // (B,S)
    const float* pemb  = (const float*)d_in[4];  // (256,H)
    const float* eemb  = (const float*)d_in[5];  // (256,H)

    float* out = (float*)d_out;
    const int main_elems = NB * NL * NH;
    const int write_tail = (out_size >= main_elems + NB) ? 1 : 0;

    dim3 grid(NL / TR, NB);      // 125 x 16 = 2000 CTAs
    dim3 block(96, 4);
    fused_kernel<<<grid, block>>>(
        (const float4*)enc, ldur, pitch, energ,
        (const float4*)pemb, (const float4*)eemb,
        (float4*)out, out + main_elems, write_tail);
}

// round 9
// speedup vs baseline: 1.2786x; 1.2786x over previous
#include <cuda_runtime.h>
#include <cstdint>

#define NB 16      // batch
#define NS 512     // seq
#define NH 384     // hidden
#define NL 2000    // max_mel_len
#define NBINS 256
#define H4 (NH/4)  // 96 float4 per row

#define TR 16                       // tile rows per CTA (125 tiles per batch row)
#define TILE_BYTES (TR * NH * 4)    // 24576

// scratch (no allocation allowed in kernel_launch)
__device__ int    g_seg[NB * NL];
__device__ int    g_mellen[NB];
__device__ float4 g_comb[NB * H4];   // pemb[pi_b] + eemb[ei_b]

// One block per batch row, 512 threads (one per source token).
__global__ void __launch_bounds__(NS) prep_kernel(
    const float* __restrict__ log_duration,
    const float* __restrict__ pitch,
    const float* __restrict__ energy,
    const float4* __restrict__ pemb,
    const float4* __restrict__ eemb,
    float* __restrict__ out_tail, int write_tail)
{
    const int b    = blockIdx.x;
    const int tid  = threadIdx.x;
    const int warp = tid >> 5;
    const int lane = tid & 31;

    __shared__ int   wsum[16];
    __shared__ float wred[16];
    __shared__ int   s_pidx, s_eidx;

    // duration = max(round(exp(ld) - 1), 0)
    const float ld = log_duration[b * NS + tid];
    const int d = (int)fmaxf(rintf(expf(ld) - 1.0f), 0.0f);

    // ---- inclusive scan over S=512: warp shfl scan + cross-warp ----
    int x = d;
    #pragma unroll
    for (int off = 1; off < 32; off <<= 1) {
        int y = __shfl_up_sync(0xffffffffu, x, off);
        if (lane >= off) x += y;
    }
    if (lane == 31) wsum[warp] = x;
    __syncthreads();
    if (warp == 0 && lane < 16) {
        int v = wsum[lane];
        #pragma unroll
        for (int off = 1; off < 16; off <<= 1) {
            int y = __shfl_up_sync(0x0000ffffu, v, off);
            if (lane >= off) v += y;
        }
        wsum[lane] = v;
    }
    __syncthreads();
    const int cum   = x + (warp ? wsum[warp - 1] : 0);
    const int start = cum - d;
    const int total = wsum[15];

    // ---- pitch / energy means via shfl reductions ----
    float p = pitch[b * NS + tid];
    float e = energy[b * NS + tid];
    #pragma unroll
    for (int off = 16; off > 0; off >>= 1) {
        p += __shfl_xor_sync(0xffffffffu, p, off);
        e += __shfl_xor_sync(0xffffffffu, e, off);
    }
    if (lane == 0) wred[warp] = p;
    __syncthreads();
    if (tid == 0) {
        float s = 0.f;
        #pragma unroll
        for (int i = 0; i < 16; i++) s += wred[i];
        s_pidx = min(max((int)(s * (1.0f / NS)), 0), NBINS - 1);
    }
    __syncthreads();
    if (lane == 0) wred[warp] = e;
    __syncthreads();
    if (tid == 0) {
        float s = 0.f;
        #pragma unroll
        for (int i = 0; i < 16; i++) s += wred[i];
        s_eidx = min(max((int)(s * (1.0f / NS)), 0), NBINS - 1);
        g_mellen[b] = min(total, NL);
        if (write_tail) out_tail[b] = (float)min(total, NL);
    }
    __syncthreads();

    // ---- combined embedding row: comb = pemb[pi] + eemb[ei] ----
    if (tid < H4) {
        float4 pv = pemb[s_pidx * H4 + tid];
        float4 ev = eemb[s_eidx * H4 + tid];
        pv.x += ev.x; pv.y += ev.y; pv.z += ev.z; pv.w += ev.w;
        g_comb[b * H4 + tid] = pv;
    }

    // ---- segment scatter (no init: expand masks rows >= mellen) ----
    const int end = min(cum, NL);
    for (int l = start; l < end; ++l) g_seg[b * NL + l] = tid;

    // all writes done -> let dependent (expand) grid proceed
    asm volatile("griddepcontrol.launch_dependents;" ::: "memory");
}

// grid (125, 16), block (96, 4). Each thread: column q, 4 consecutive rows.
// Tile built in smem, one 24KB TMA bulk store. PDL: launched concurrently
// with prep, waits on griddepcontrol before consuming prep outputs.
__global__ void __launch_bounds__(384) expand_kernel(
    const float4* __restrict__ enc,
    float4* __restrict__ out)
{
    __shared__ __align__(128) float4 tile[TR * H4];   // 24 KB

    const int q  = threadIdx.x;                 // 0..95
    const int yy = threadIdx.y;                 // 0..3
    const int b  = blockIdx.y;                  // 0..15
    const int l0 = blockIdx.x * TR;             // tile base row
    const int r0 = yy * 4;                      // my 4 consecutive rows

    // precompute everything independent of prep outputs
    const float4* __restrict__ encb = enc + b * (NS * H4);
    const int* __restrict__ segp = g_seg + b * NL + l0 + r0;
    uint32_t sbase;
    asm("{ .reg .u64 t; cvta.to.shared.u64 t, %1; cvt.u32.u64 %0, t; }"
        : "=r"(sbase) : "l"((const void*)tile));

    // wait for prep grid's writes to be visible
    asm volatile("griddepcontrol.wait;" ::: "memory");

    const int ml = g_mellen[b];
    const int4 s4 = *(const int4*)segp;
    const float4 c = g_comb[b * H4 + q];

    const int sc[4] = { s4.x, s4.y, s4.z, s4.w };

    // front-batched unconditional gather loads (clamped addresses)
    float4 ev[4];
    #pragma unroll
    for (int i = 0; i < 4; i++) {
        const int s = min(max(sc[i], 0), NS - 1);
        ev[i] = __ldg(&encb[s * H4 + q]);
    }

    // masked add + STS
    #pragma unroll
    for (int i = 0; i < 4; i++) {
        const float m = (l0 + r0 + i < ml) ? 1.0f : 0.0f;
        float4 v;
        v.x = fmaf(m, ev[i].x, c.x);
        v.y = fmaf(m, ev[i].y, c.y);
        v.z = fmaf(m, ev[i].z, c.z);
        v.w = fmaf(m, ev[i].w, c.w);
        tile[(r0 + i) * H4 + q] = v;
    }
    __syncthreads();

    if (q == 0 && yy == 0) {
        const float4* gdst = out + (size_t)(b * NL + l0) * H4;
        asm volatile("fence.proxy.async.shared::cta;" ::: "memory");
        asm volatile(
            "cp.async.bulk.global.shared::cta.bulk_group [%0], [%1], %2;"
            :: "l"(gdst), "r"(sbase), "n"(TILE_BYTES) : "memory");
        asm volatile("cp.async.bulk.commit_group;" ::: "memory");
        asm volatile("cp.async.bulk.wait_group.read 0;" ::: "memory");
    }
}

extern "C" void kernel_launch(void* const* d_in, const int* in_sizes, int n_in,
                              void* d_out, int out_size)
{
    const float* enc   = (const float*)d_in[0];  // (B,S,H)
    const float* ldur  = (const float*)d_in[1];  // (B,S)
    const float* pitch = (const float*)d_in[2];  // (B,S)
    const float* energ = (const float*)d_in[3];  // (B,S)
    const float* pemb  = (const float*)d_in[4];  // (256,H)
    const float* eemb  = (const float*)d_in[5];  // (256,H)

    float* out = (float*)d_out;
    const int main_elems = NB * NL * NH;
    const int write_tail = (out_size >= main_elems + NB) ? 1 : 0;

    prep_kernel<<<NB, NS>>>(ldur, pitch, energ,
                            (const float4*)pemb, (const float4*)eemb,
                            out + main_elems, write_tail);

    // expand with Programmatic Dependent Launch: overlaps with prep
    cudaLaunchConfig_t cfg = {};
    cfg.gridDim  = dim3(NL / TR, NB);   // 125 x 16
    cfg.blockDim = dim3(96, 4);
    cfg.stream   = 0;                   // legacy default (capture) stream
    cudaLaunchAttribute attr[1];
    attr[0].id = cudaLaunchAttributeProgrammaticStreamSerialization;
    attr[0].val.programmaticStreamSerializationAllowed = 1;
    cfg.attrs = attr;
    cfg.numAttrs = 1;
    cudaLaunchKernelEx(&cfg, expand_kernel, (const float4*)enc, (float4*)out);
}